// round 3
// baseline (speedup 1.0000x reference)
#include <cuda_runtime.h>
#include <math.h>

// Problem constants
#define BB 4
#define LL 1024
#define DD 1024
#define HH 16
#define HD 64
#define EE 16384
#define D3 3072

// ---------------------------------------------------------------------------
// Scratch (static device globals; no allocation allowed)
// ---------------------------------------------------------------------------
__device__ float g_q[(size_t)BB * HH * LL * HD];     // [B,H,L,HD], pre-scaled by 1/8
__device__ float g_k[(size_t)BB * HH * LL * HD];     // [B,H,L,HD]
__device__ float g_v[(size_t)BB * HH * LL * HD];     // [B,H,L,HD]
__device__ float g_attn[(size_t)BB * LL * DD];       // [B,L,D] attention output
__device__ unsigned g_adj[LL * (LL / 32)];           // bitmask: bit k of row q

// ---------------------------------------------------------------------------
// Kernel 1a: clear adjacency
// ---------------------------------------------------------------------------
__global__ void adj_clear_k() {
    int i = blockIdx.x * blockDim.x + threadIdx.x;
    if (i < LL * (LL / 32)) g_adj[i] = 0u;
}

// Kernel 1b: scatter edges (symmetric)
__global__ void adj_scatter_k(const int* __restrict__ edges) {
    int e = blockIdx.x * blockDim.x + threadIdx.x;
    if (e >= EE) return;
    int a = edges[2 * e + 0];
    int b = edges[2 * e + 1];
    atomicOr(&g_adj[a * 32 + (b >> 5)], 1u << (b & 31));
    atomicOr(&g_adj[b * 32 + (a >> 5)], 1u << (a & 31));
}

// ---------------------------------------------------------------------------
// Tiled SGEMM: C[m,n] = sum_k A[m,k] * Bm[n,k] + bias[n]
// A: [M,1024] row-major, Bm: [N,1024] row-major (both K-fastest).
// BM=BN=128, BK=8, 256 threads, 8x8 per-thread microtile.
// MODE 1: QKV -> scatter into g_q/g_k/g_v head layout, scale q by 0.125
// MODE 0: out-proj -> C row-major [M,1024], A read from g_attn
// ---------------------------------------------------------------------------
template <int MODE>
__global__ void __launch_bounds__(256) sgemm_k(const float* __restrict__ A_in,
                                               const float* __restrict__ Bmat,
                                               const float* __restrict__ bias,
                                               float* __restrict__ Cout) {
    constexpr int K = 1024;
    const float* A = (MODE == 0) ? (const float*)g_attn : A_in;

    __shared__ float As[8][128];
    __shared__ float Bs[8][128];

    const int tid = threadIdx.x;
    const int m0 = blockIdx.y * 128;
    const int n0 = blockIdx.x * 128;

    const int lr = tid >> 1;          // 0..127
    const int lk = (tid & 1) * 4;     // 0 or 4

    const float* Aload = A + (size_t)(m0 + lr) * K + lk;
    const float* Bload = Bmat + (size_t)(n0 + lr) * K + lk;

    float acc[8][8];
#pragma unroll
    for (int i = 0; i < 8; i++)
#pragma unroll
        for (int j = 0; j < 8; j++) acc[i][j] = 0.f;

    const int tr = tid >> 4;   // 0..15
    const int tc = tid & 15;   // 0..15

    for (int k0 = 0; k0 < K; k0 += 8) {
        float4 a4 = *(const float4*)(Aload + k0);
        float4 b4 = *(const float4*)(Bload + k0);
        __syncthreads();
        As[lk + 0][lr] = a4.x; As[lk + 1][lr] = a4.y;
        As[lk + 2][lr] = a4.z; As[lk + 3][lr] = a4.w;
        Bs[lk + 0][lr] = b4.x; Bs[lk + 1][lr] = b4.y;
        Bs[lk + 2][lr] = b4.z; Bs[lk + 3][lr] = b4.w;
        __syncthreads();

#pragma unroll
        for (int kk = 0; kk < 8; kk++) {
            float4 ra0 = *(const float4*)&As[kk][tr * 8];
            float4 ra1 = *(const float4*)&As[kk][tr * 8 + 4];
            float4 rb0 = *(const float4*)&Bs[kk][tc * 8];
            float4 rb1 = *(const float4*)&Bs[kk][tc * 8 + 4];
            float ra[8] = {ra0.x, ra0.y, ra0.z, ra0.w, ra1.x, ra1.y, ra1.z, ra1.w};
            float rb[8] = {rb0.x, rb0.y, rb0.z, rb0.w, rb1.x, rb1.y, rb1.z, rb1.w};
#pragma unroll
            for (int i = 0; i < 8; i++)
#pragma unroll
                for (int j = 0; j < 8; j++) acc[i][j] += ra[i] * rb[j];
        }
    }

    if (MODE == 1) {
        // QKV scatter into [B,H,L,HD]; q pre-scaled by 1/sqrt(HD)=0.125
        const int part = n0 >> 10;  // tile of 128 never crosses a 1024 boundary
        float* dstbase = (part == 0) ? g_q : (part == 1) ? g_k : g_v;
        const float qscale = (part == 0) ? 0.125f : 1.0f;
#pragma unroll
        for (int i = 0; i < 8; i++) {
            int m = m0 + tr * 8 + i;
            int bb = m >> 10;
            int ll = m & 1023;
#pragma unroll
            for (int j = 0; j < 8; j++) {
                int n = n0 + tc * 8 + j;
                int nn = n & 1023;
                int h = nn >> 6;
                int d = nn & 63;
                float v = (acc[i][j] + bias[n]) * qscale;
                dstbase[(((size_t)bb * HH + h) * LL + ll) * HD + d] = v;
            }
        }
    } else {
#pragma unroll
        for (int i = 0; i < 8; i++) {
            int m = m0 + tr * 8 + i;
#pragma unroll
            for (int j = 0; j < 8; j++) {
                int n = n0 + tc * 8 + j;
                Cout[(size_t)m * DD + n] = acc[i][j] + bias[n];
            }
        }
    }
}

// ---------------------------------------------------------------------------
// Kernel 3: masked flash attention. One thread per query row.
// grid = (L/128, B*H), block = 128.  K/V tiles 64x64 fp32 in smem (32KB).
// Mask semantics (reference): adj bit set -> score = -inf (excluded).
// ---------------------------------------------------------------------------
__global__ void __launch_bounds__(128) attn_k() {
    const int bh = blockIdx.y;          // b*H + h
    const int tid = threadIdx.x;
    const int q = blockIdx.x * 128 + tid;

    const float* Qp = g_q + ((size_t)bh * LL + q) * HD;
    float4 qv[16];
#pragma unroll
    for (int i = 0; i < 16; i++) qv[i] = *(const float4*)(Qp + i * 4);

    float4 ov[16];
#pragma unroll
    for (int i = 0; i < 16; i++) ov[i] = make_float4(0.f, 0.f, 0.f, 0.f);
    float mrun = -INFINITY;
    float lsum = 0.f;

    __shared__ float4 Ks[64 * 16];
    __shared__ float4 Vs[64 * 16];

    const float4* Kg = (const float4*)(g_k + (size_t)bh * LL * HD);
    const float4* Vg = (const float4*)(g_v + (size_t)bh * LL * HD);
    const unsigned* adjrow = g_adj + q * 32;

    for (int k0 = 0; k0 < LL; k0 += 64) {
        __syncthreads();
#pragma unroll
        for (int i = 0; i < 8; i++) {
            Ks[tid + i * 128] = Kg[k0 * 16 + tid + i * 128];
            Vs[tid + i * 128] = Vg[k0 * 16 + tid + i * 128];
        }
        __syncthreads();

        unsigned long long msk =
            ((unsigned long long)adjrow[(k0 >> 5) + 1] << 32) |
            (unsigned long long)adjrow[k0 >> 5];

        for (int kk = 0; kk < 64; kk++) {
            if ((msk >> kk) & 1ULL) continue;   // edge present -> masked out
            const float4* Kr = &Ks[kk * 16];
            float s = 0.f;
#pragma unroll
            for (int i = 0; i < 16; i++) {
                float4 kvv = Kr[i];
                s += qv[i].x * kvv.x + qv[i].y * kvv.y +
                     qv[i].z * kvv.z + qv[i].w * kvv.w;
            }
            const float4* Vr = &Vs[kk * 16];
            if (s <= mrun) {
                float p = __expf(s - mrun);
                lsum += p;
#pragma unroll
                for (int i = 0; i < 16; i++) {
                    float4 vv = Vr[i];
                    ov[i].x += p * vv.x; ov[i].y += p * vv.y;
                    ov[i].z += p * vv.z; ov[i].w += p * vv.w;
                }
            } else {
                float c = __expf(mrun - s);   // expf(-inf)=0 handles first hit
                mrun = s;
                lsum = lsum * c + 1.f;
#pragma unroll
                for (int i = 0; i < 16; i++) {
                    float4 vv = Vr[i];
                    ov[i].x = ov[i].x * c + vv.x;
                    ov[i].y = ov[i].y * c + vv.y;
                    ov[i].z = ov[i].z * c + vv.z;
                    ov[i].w = ov[i].w * c + vv.w;
                }
            }
        }
    }

    const float inv = 1.f / lsum;
    const int b = bh >> 4;
    const int h = bh & 15;
    float* outp = g_attn + ((size_t)(b * LL + q)) * DD + h * HD;
#pragma unroll
    for (int i = 0; i < 16; i++) {
        float4 o = ov[i];
        o.x *= inv; o.y *= inv; o.z *= inv; o.w *= inv;
        *(float4*)(outp + i * 4) = o;
    }
}

// ---------------------------------------------------------------------------
// Launch
// ---------------------------------------------------------------------------
extern "C" void kernel_launch(void* const* d_in, const int* in_sizes, int n_in,
                              void* d_out, int out_size) {
    const float* x     = (const float*)d_in[0];   // [B,L,D]
    const int*   edges = (const int*)d_in[1];     // [E,2]
    const float* w_qkv = (const float*)d_in[2];   // [3D,D]
    const float* b_qkv = (const float*)d_in[3];   // [3D]
    const float* w_out = (const float*)d_in[4];   // [D,D]
    const float* b_out = (const float*)d_in[5];   // [D]
    float* out = (float*)d_out;                   // [B,L,D]

    // 1) adjacency bitmask
    adj_clear_k<<<(LL * 32 + 255) / 256, 256>>>();
    adj_scatter_k<<<(EE + 255) / 256, 256>>>(edges);

    // 2) fused QKV projection (+bias, +q scaling, +head-layout scatter)
    {
        dim3 grid(D3 / 128, (BB * LL) / 128);   // 24 x 32
        sgemm_k<1><<<grid, 256>>>(x, w_qkv, b_qkv, nullptr);
    }

    // 3) masked attention
    {
        dim3 grid(LL / 128, BB * HH);           // 8 x 64
        attn_k<<<grid, 128>>>();
    }

    // 4) output projection (+bias) -> d_out
    {
        dim3 grid(DD / 128, (BB * LL) / 128);   // 8 x 32
        sgemm_k<0><<<grid, 256>>>(nullptr, w_out, b_out, out);
    }
}

// round 4
// speedup vs baseline: 1.7120x; 1.7120x over previous
#include <cuda_runtime.h>
#include <math.h>

// Problem constants
#define BB 4
#define LL 1024
#define DD 1024
#define HH 16
#define HD 64
#define EE 16384
#define D3 3072

// ---------------------------------------------------------------------------
// Scratch (static device globals; no allocation allowed)
// ---------------------------------------------------------------------------
__device__ float g_q[(size_t)BB * HH * LL * HD];     // [B,H,L,HD], pre-scaled by 1/8
__device__ float g_k[(size_t)BB * HH * LL * HD];     // [B,H,L,HD]
__device__ float g_v[(size_t)BB * HH * LL * HD];     // [B,H,L,HD]
__device__ float g_attn[(size_t)BB * LL * DD];       // [B,L,D] attention output
__device__ unsigned g_adj[LL * (LL / 32)];           // bitmask: bit k of row q

// ---------------------------------------------------------------------------
// Kernel 1a: clear adjacency
// ---------------------------------------------------------------------------
__global__ void adj_clear_k() {
    int i = blockIdx.x * blockDim.x + threadIdx.x;
    if (i < LL * (LL / 32)) g_adj[i] = 0u;
}

// Kernel 1b: scatter edges (symmetric)
__global__ void adj_scatter_k(const int* __restrict__ edges) {
    int e = blockIdx.x * blockDim.x + threadIdx.x;
    if (e >= EE) return;
    int a = edges[2 * e + 0];
    int b = edges[2 * e + 1];
    atomicOr(&g_adj[a * 32 + (b >> 5)], 1u << (b & 31));
    atomicOr(&g_adj[b * 32 + (a >> 5)], 1u << (a & 31));
}

// ---------------------------------------------------------------------------
// tf32 helpers
// ---------------------------------------------------------------------------
__device__ __forceinline__ unsigned f2tf32(float f) {
    unsigned u;
    asm("cvt.rna.tf32.f32 %0, %1;" : "=r"(u) : "f"(f));
    return u;
}

__device__ __forceinline__ void mma_tf32(float* d, const unsigned* a,
                                         unsigned b0, unsigned b1) {
    asm volatile(
        "mma.sync.aligned.m16n8k8.row.col.f32.tf32.tf32.f32 "
        "{%0,%1,%2,%3}, {%4,%5,%6,%7}, {%8,%9}, {%0,%1,%2,%3};"
        : "+f"(d[0]), "+f"(d[1]), "+f"(d[2]), "+f"(d[3])
        : "r"(a[0]), "r"(a[1]), "r"(a[2]), "r"(a[3]), "r"(b0), "r"(b1));
}

// ---------------------------------------------------------------------------
// TF32 tensor-core GEMM: C[m,n] = sum_k A[m,k] * Bm[n,k] + bias[n]
// A: [M,1024] row-major, Bm: [N,1024] row-major (both K-fastest).
// BM=BN=128, BK=32, 256 threads = 8 warps (2x4), warp tile 64x32,
// m16n8k8 tf32 mma, 4x4 mma-frag grid per warp.
// Smem stride 36 floats -> fragment LDS bank = (4g+t)%32, conflict-free.
// MODE 1: QKV -> scatter into g_q/g_k/g_v head layout, scale q by 0.125
// MODE 0: out-proj -> C row-major [M,1024], A read from g_attn
// ---------------------------------------------------------------------------
#define SSTR 36

template <int MODE>
__global__ void __launch_bounds__(256, 2) mma_gemm_k(const float* __restrict__ A_in,
                                                     const float* __restrict__ Bmat,
                                                     const float* __restrict__ bias,
                                                     float* __restrict__ Cout) {
    constexpr int K = 1024;
    const float* A = (MODE == 0) ? (const float*)g_attn : A_in;

    __shared__ unsigned As[128][SSTR];
    __shared__ unsigned Bs[128][SSTR];

    const int tid = threadIdx.x;
    const int m0 = blockIdx.y * 128;
    const int n0 = blockIdx.x * 128;

    // Global staging: 2 threads per row, 16 k-floats each
    const int lrow = tid >> 1;            // 0..127
    const int lk   = (tid & 1) * 16;      // 0 or 16
    const float* Ag = A    + (size_t)(m0 + lrow) * K + lk;
    const float* Bg = Bmat + (size_t)(n0 + lrow) * K + lk;

    // Warp layout
    const int wid  = tid >> 5;
    const int lane = tid & 31;
    const int wm   = (wid & 1) * 64;      // warp M offset in tile
    const int wn   = (wid >> 1) * 32;     // warp N offset in tile
    const int g    = lane >> 2;           // 0..7
    const int t    = lane & 3;            // 0..3

    float acc[4][4][4];
#pragma unroll
    for (int mi = 0; mi < 4; mi++)
#pragma unroll
        for (int ni = 0; ni < 4; ni++)
#pragma unroll
            for (int e = 0; e < 4; e++) acc[mi][ni][e] = 0.f;

    // Prefetch first tile
    float4 pa0 = *(const float4*)(Ag + 0);
    float4 pa1 = *(const float4*)(Ag + 4);
    float4 pa2 = *(const float4*)(Ag + 8);
    float4 pa3 = *(const float4*)(Ag + 12);
    float4 pb0 = *(const float4*)(Bg + 0);
    float4 pb1 = *(const float4*)(Bg + 4);
    float4 pb2 = *(const float4*)(Bg + 8);
    float4 pb3 = *(const float4*)(Bg + 12);

    for (int k0 = 0; k0 < K; k0 += 32) {
        __syncthreads();   // prior compute done before overwrite
        // Store converted tf32 into smem
        As[lrow][lk + 0]  = f2tf32(pa0.x); As[lrow][lk + 1]  = f2tf32(pa0.y);
        As[lrow][lk + 2]  = f2tf32(pa0.z); As[lrow][lk + 3]  = f2tf32(pa0.w);
        As[lrow][lk + 4]  = f2tf32(pa1.x); As[lrow][lk + 5]  = f2tf32(pa1.y);
        As[lrow][lk + 6]  = f2tf32(pa1.z); As[lrow][lk + 7]  = f2tf32(pa1.w);
        As[lrow][lk + 8]  = f2tf32(pa2.x); As[lrow][lk + 9]  = f2tf32(pa2.y);
        As[lrow][lk + 10] = f2tf32(pa2.z); As[lrow][lk + 11] = f2tf32(pa2.w);
        As[lrow][lk + 12] = f2tf32(pa3.x); As[lrow][lk + 13] = f2tf32(pa3.y);
        As[lrow][lk + 14] = f2tf32(pa3.z); As[lrow][lk + 15] = f2tf32(pa3.w);
        Bs[lrow][lk + 0]  = f2tf32(pb0.x); Bs[lrow][lk + 1]  = f2tf32(pb0.y);
        Bs[lrow][lk + 2]  = f2tf32(pb0.z); Bs[lrow][lk + 3]  = f2tf32(pb0.w);
        Bs[lrow][lk + 4]  = f2tf32(pb1.x); Bs[lrow][lk + 5]  = f2tf32(pb1.y);
        Bs[lrow][lk + 6]  = f2tf32(pb1.z); Bs[lrow][lk + 7]  = f2tf32(pb1.w);
        Bs[lrow][lk + 8]  = f2tf32(pb2.x); Bs[lrow][lk + 9]  = f2tf32(pb2.y);
        Bs[lrow][lk + 10] = f2tf32(pb2.z); Bs[lrow][lk + 11] = f2tf32(pb2.w);
        Bs[lrow][lk + 12] = f2tf32(pb3.x); Bs[lrow][lk + 13] = f2tf32(pb3.y);
        Bs[lrow][lk + 14] = f2tf32(pb3.z); Bs[lrow][lk + 15] = f2tf32(pb3.w);
        __syncthreads();

        // Prefetch next tile (overlaps with mma work below)
        if (k0 + 32 < K) {
            pa0 = *(const float4*)(Ag + k0 + 32);
            pa1 = *(const float4*)(Ag + k0 + 36);
            pa2 = *(const float4*)(Ag + k0 + 40);
            pa3 = *(const float4*)(Ag + k0 + 44);
            pb0 = *(const float4*)(Bg + k0 + 32);
            pb1 = *(const float4*)(Bg + k0 + 36);
            pb2 = *(const float4*)(Bg + k0 + 40);
            pb3 = *(const float4*)(Bg + k0 + 44);
        }

#pragma unroll
        for (int ks = 0; ks < 4; ks++) {
            const int kb = ks * 8 + t;
            unsigned af[4][4];
#pragma unroll
            for (int mi = 0; mi < 4; mi++) {
                const int r = wm + mi * 16 + g;
                af[mi][0] = As[r][kb];
                af[mi][1] = As[r + 8][kb];
                af[mi][2] = As[r][kb + 4];
                af[mi][3] = As[r + 8][kb + 4];
            }
            unsigned bf0[4], bf1[4];
#pragma unroll
            for (int ni = 0; ni < 4; ni++) {
                const int c = wn + ni * 8 + g;
                bf0[ni] = Bs[c][kb];
                bf1[ni] = Bs[c][kb + 4];
            }
#pragma unroll
            for (int mi = 0; mi < 4; mi++)
#pragma unroll
                for (int ni = 0; ni < 4; ni++)
                    mma_tf32(acc[mi][ni], af[mi], bf0[ni], bf1[ni]);
        }
    }

    // Epilogue
    const int g2t = 2 * t;
    if (MODE == 1) {
        const int part = n0 >> 10;   // 128-tile never crosses a 1024 boundary
        float* dstbase = (part == 0) ? g_q : (part == 1) ? g_k : g_v;
        const float qs = (part == 0) ? 0.125f : 1.0f;
#pragma unroll
        for (int mi = 0; mi < 4; mi++) {
#pragma unroll
            for (int half = 0; half < 2; half++) {
                const int m  = m0 + wm + mi * 16 + g + half * 8;
                const int bb = m >> 10;
                const int ll = m & 1023;
#pragma unroll
                for (int ni = 0; ni < 4; ni++) {
                    const int col = n0 + wn + ni * 8 + g2t;
                    const int nn  = col & 1023;
                    const int h   = nn >> 6;
                    const int d   = nn & 63;
                    float* p = dstbase +
                               (((size_t)bb * HH + h) * LL + ll) * HD + d;
                    p[0] = (acc[mi][ni][half * 2 + 0] + bias[col]) * qs;
                    p[1] = (acc[mi][ni][half * 2 + 1] + bias[col + 1]) * qs;
                }
            }
        }
    } else {
#pragma unroll
        for (int mi = 0; mi < 4; mi++) {
#pragma unroll
            for (int half = 0; half < 2; half++) {
                const int m = m0 + wm + mi * 16 + g + half * 8;
#pragma unroll
                for (int ni = 0; ni < 4; ni++) {
                    const int col = n0 + wn + ni * 8 + g2t;
                    float* p = Cout + (size_t)m * DD + col;
                    p[0] = acc[mi][ni][half * 2 + 0] + bias[col];
                    p[1] = acc[mi][ni][half * 2 + 1] + bias[col + 1];
                }
            }
        }
    }
}

// ---------------------------------------------------------------------------
// Kernel 3: masked flash attention. One thread per query row.
// grid = (L/128, B*H), block = 128.  K/V tiles 64x64 fp32 in smem (32KB).
// Dot product split into 4 partial sums to break the FFMA RAW chain.
// Mask semantics (reference): adj bit set -> score = -inf (excluded).
// ---------------------------------------------------------------------------
__global__ void __launch_bounds__(128) attn_k() {
    const int bh = blockIdx.y;          // b*H + h
    const int tid = threadIdx.x;
    const int q = blockIdx.x * 128 + tid;

    const float* Qp = g_q + ((size_t)bh * LL + q) * HD;
    float4 qv[16];
#pragma unroll
    for (int i = 0; i < 16; i++) qv[i] = *(const float4*)(Qp + i * 4);

    float4 ov[16];
#pragma unroll
    for (int i = 0; i < 16; i++) ov[i] = make_float4(0.f, 0.f, 0.f, 0.f);
    float mrun = -INFINITY;
    float lsum = 0.f;

    __shared__ float4 Ks[64 * 16];
    __shared__ float4 Vs[64 * 16];

    const float4* Kg = (const float4*)(g_k + (size_t)bh * LL * HD);
    const float4* Vg = (const float4*)(g_v + (size_t)bh * LL * HD);
    const unsigned* adjrow = g_adj + q * 32;

    for (int k0 = 0; k0 < LL; k0 += 64) {
        __syncthreads();
#pragma unroll
        for (int i = 0; i < 8; i++) {
            Ks[tid + i * 128] = Kg[k0 * 16 + tid + i * 128];
            Vs[tid + i * 128] = Vg[k0 * 16 + tid + i * 128];
        }
        __syncthreads();

        unsigned long long msk =
            ((unsigned long long)adjrow[(k0 >> 5) + 1] << 32) |
            (unsigned long long)adjrow[k0 >> 5];

        for (int kk = 0; kk < 64; kk++) {
            if ((msk >> kk) & 1ULL) continue;   // edge present -> masked out
            const float4* Kr = &Ks[kk * 16];
            // 4 independent partial dot products (chain depth /4)
            float s0 = 0.f, s1 = 0.f, s2 = 0.f, s3 = 0.f;
#pragma unroll
            for (int i = 0; i < 16; i += 4) {
                float4 kv0 = Kr[i + 0];
                float4 kv1 = Kr[i + 1];
                float4 kv2 = Kr[i + 2];
                float4 kv3 = Kr[i + 3];
                s0 += qv[i + 0].x * kv0.x + qv[i + 0].y * kv0.y +
                      qv[i + 0].z * kv0.z + qv[i + 0].w * kv0.w;
                s1 += qv[i + 1].x * kv1.x + qv[i + 1].y * kv1.y +
                      qv[i + 1].z * kv1.z + qv[i + 1].w * kv1.w;
                s2 += qv[i + 2].x * kv2.x + qv[i + 2].y * kv2.y +
                      qv[i + 2].z * kv2.z + qv[i + 2].w * kv2.w;
                s3 += qv[i + 3].x * kv3.x + qv[i + 3].y * kv3.y +
                      qv[i + 3].z * kv3.z + qv[i + 3].w * kv3.w;
            }
            float s = (s0 + s1) + (s2 + s3);

            const float4* Vr = &Vs[kk * 16];
            if (s <= mrun) {
                float p = __expf(s - mrun);
                lsum += p;
#pragma unroll
                for (int i = 0; i < 16; i++) {
                    float4 vv = Vr[i];
                    ov[i].x += p * vv.x; ov[i].y += p * vv.y;
                    ov[i].z += p * vv.z; ov[i].w += p * vv.w;
                }
            } else {
                float c = __expf(mrun - s);   // expf(-inf)=0 handles first hit
                mrun = s;
                lsum = lsum * c + 1.f;
#pragma unroll
                for (int i = 0; i < 16; i++) {
                    float4 vv = Vr[i];
                    ov[i].x = ov[i].x * c + vv.x;
                    ov[i].y = ov[i].y * c + vv.y;
                    ov[i].z = ov[i].z * c + vv.z;
                    ov[i].w = ov[i].w * c + vv.w;
                }
            }
        }
    }

    const float inv = 1.f / lsum;
    const int b = bh >> 4;
    const int h = bh & 15;
    float* outp = g_attn + ((size_t)(b * LL + q)) * DD + h * HD;
#pragma unroll
    for (int i = 0; i < 16; i++) {
        float4 o = ov[i];
        o.x *= inv; o.y *= inv; o.z *= inv; o.w *= inv;
        *(float4*)(outp + i * 4) = o;
    }
}

// ---------------------------------------------------------------------------
// Launch
// ---------------------------------------------------------------------------
extern "C" void kernel_launch(void* const* d_in, const int* in_sizes, int n_in,
                              void* d_out, int out_size) {
    const float* x     = (const float*)d_in[0];   // [B,L,D]
    const int*   edges = (const int*)d_in[1];     // [E,2]
    const float* w_qkv = (const float*)d_in[2];   // [3D,D]
    const float* b_qkv = (const float*)d_in[3];   // [3D]
    const float* w_out = (const float*)d_in[4];   // [D,D]
    const float* b_out = (const float*)d_in[5];   // [D]
    float* out = (float*)d_out;                   // [B,L,D]

    // 1) adjacency bitmask
    adj_clear_k<<<(LL * 32 + 255) / 256, 256>>>();
    adj_scatter_k<<<(EE + 255) / 256, 256>>>(edges);

    // 2) fused QKV projection (+bias, +q scaling, +head-layout scatter) [tf32 TC]
    {
        dim3 grid(D3 / 128, (BB * LL) / 128);   // 24 x 32
        mma_gemm_k<1><<<grid, 256>>>(x, w_qkv, b_qkv, nullptr);
    }

    // 3) masked attention
    {
        dim3 grid(LL / 128, BB * HH);           // 8 x 64
        attn_k<<<grid, 128>>>();
    }

    // 4) output projection (+bias) -> d_out [tf32 TC]
    {
        dim3 grid(DD / 128, (BB * LL) / 128);   // 8 x 32
        mma_gemm_k<0><<<grid, 256>>>(nullptr, w_out, b_out, out);
    }
}

// round 5
// speedup vs baseline: 3.2231x; 1.8827x over previous
#include <cuda_runtime.h>
#include <math.h>

// Problem constants
#define BB 4
#define LL 1024
#define DD 1024
#define HH 16
#define HD 64
#define EE 16384
#define D3 3072

#define NEGF (-1e30f)

// ---------------------------------------------------------------------------
// Scratch (static device globals; no allocation allowed)
// ---------------------------------------------------------------------------
__device__ float g_q[(size_t)BB * HH * LL * HD];     // [B,H,L,HD], pre-scaled by 1/8, tf32-ok
__device__ float g_k[(size_t)BB * HH * LL * HD];     // [B,H,L,HD]
__device__ float g_v[(size_t)BB * HH * LL * HD];     // [B,H,L,HD]
__device__ float g_attn[(size_t)BB * LL * DD];       // [B,L,D] attention output
__device__ unsigned g_adj[LL * (LL / 32)];           // bitmask: bit k of row q

// ---------------------------------------------------------------------------
// Kernel 1a: clear adjacency
// ---------------------------------------------------------------------------
__global__ void adj_clear_k() {
    int i = blockIdx.x * blockDim.x + threadIdx.x;
    if (i < LL * (LL / 32)) g_adj[i] = 0u;
}

// Kernel 1b: scatter edges (symmetric)
__global__ void adj_scatter_k(const int* __restrict__ edges) {
    int e = blockIdx.x * blockDim.x + threadIdx.x;
    if (e >= EE) return;
    int a = edges[2 * e + 0];
    int b = edges[2 * e + 1];
    atomicOr(&g_adj[a * 32 + (b >> 5)], 1u << (b & 31));
    atomicOr(&g_adj[b * 32 + (a >> 5)], 1u << (a & 31));
}

// ---------------------------------------------------------------------------
// tf32 helpers
// ---------------------------------------------------------------------------
__device__ __forceinline__ unsigned f2tf32(float f) {
    unsigned u;
    asm("cvt.rna.tf32.f32 %0, %1;" : "=r"(u) : "f"(f));
    return u;
}

__device__ __forceinline__ void mma_tf32(float* d, const unsigned* a,
                                         unsigned b0, unsigned b1) {
    asm volatile(
        "mma.sync.aligned.m16n8k8.row.col.f32.tf32.tf32.f32 "
        "{%0,%1,%2,%3}, {%4,%5,%6,%7}, {%8,%9}, {%0,%1,%2,%3};"
        : "+f"(d[0]), "+f"(d[1]), "+f"(d[2]), "+f"(d[3])
        : "r"(a[0]), "r"(a[1]), "r"(a[2]), "r"(a[3]), "r"(b0), "r"(b1));
}

// ---------------------------------------------------------------------------
// TF32 tensor-core GEMM: C[m,n] = sum_k A[m,k] * Bm[n,k] + bias[n]
// (unchanged from round 3 — already near tf32 roofline for these shapes)
// ---------------------------------------------------------------------------
#define SSTR 36

template <int MODE>
__global__ void __launch_bounds__(256, 2) mma_gemm_k(const float* __restrict__ A_in,
                                                     const float* __restrict__ Bmat,
                                                     const float* __restrict__ bias,
                                                     float* __restrict__ Cout) {
    constexpr int K = 1024;
    const float* A = (MODE == 0) ? (const float*)g_attn : A_in;

    __shared__ unsigned As[128][SSTR];
    __shared__ unsigned Bs[128][SSTR];

    const int tid = threadIdx.x;
    const int m0 = blockIdx.y * 128;
    const int n0 = blockIdx.x * 128;

    const int lrow = tid >> 1;
    const int lk   = (tid & 1) * 16;
    const float* Ag = A    + (size_t)(m0 + lrow) * K + lk;
    const float* Bg = Bmat + (size_t)(n0 + lrow) * K + lk;

    const int wid  = tid >> 5;
    const int lane = tid & 31;
    const int wm   = (wid & 1) * 64;
    const int wn   = (wid >> 1) * 32;
    const int g    = lane >> 2;
    const int t    = lane & 3;

    float acc[4][4][4];
#pragma unroll
    for (int mi = 0; mi < 4; mi++)
#pragma unroll
        for (int ni = 0; ni < 4; ni++)
#pragma unroll
            for (int e = 0; e < 4; e++) acc[mi][ni][e] = 0.f;

    float4 pa0 = *(const float4*)(Ag + 0);
    float4 pa1 = *(const float4*)(Ag + 4);
    float4 pa2 = *(const float4*)(Ag + 8);
    float4 pa3 = *(const float4*)(Ag + 12);
    float4 pb0 = *(const float4*)(Bg + 0);
    float4 pb1 = *(const float4*)(Bg + 4);
    float4 pb2 = *(const float4*)(Bg + 8);
    float4 pb3 = *(const float4*)(Bg + 12);

    for (int k0 = 0; k0 < K; k0 += 32) {
        __syncthreads();
        As[lrow][lk + 0]  = f2tf32(pa0.x); As[lrow][lk + 1]  = f2tf32(pa0.y);
        As[lrow][lk + 2]  = f2tf32(pa0.z); As[lrow][lk + 3]  = f2tf32(pa0.w);
        As[lrow][lk + 4]  = f2tf32(pa1.x); As[lrow][lk + 5]  = f2tf32(pa1.y);
        As[lrow][lk + 6]  = f2tf32(pa1.z); As[lrow][lk + 7]  = f2tf32(pa1.w);
        As[lrow][lk + 8]  = f2tf32(pa2.x); As[lrow][lk + 9]  = f2tf32(pa2.y);
        As[lrow][lk + 10] = f2tf32(pa2.z); As[lrow][lk + 11] = f2tf32(pa2.w);
        As[lrow][lk + 12] = f2tf32(pa3.x); As[lrow][lk + 13] = f2tf32(pa3.y);
        As[lrow][lk + 14] = f2tf32(pa3.z); As[lrow][lk + 15] = f2tf32(pa3.w);
        Bs[lrow][lk + 0]  = f2tf32(pb0.x); Bs[lrow][lk + 1]  = f2tf32(pb0.y);
        Bs[lrow][lk + 2]  = f2tf32(pb0.z); Bs[lrow][lk + 3]  = f2tf32(pb0.w);
        Bs[lrow][lk + 4]  = f2tf32(pb1.x); Bs[lrow][lk + 5]  = f2tf32(pb1.y);
        Bs[lrow][lk + 6]  = f2tf32(pb1.z); Bs[lrow][lk + 7]  = f2tf32(pb1.w);
        Bs[lrow][lk + 8]  = f2tf32(pb2.x); Bs[lrow][lk + 9]  = f2tf32(pb2.y);
        Bs[lrow][lk + 10] = f2tf32(pb2.z); Bs[lrow][lk + 11] = f2tf32(pb2.w);
        Bs[lrow][lk + 12] = f2tf32(pb3.x); Bs[lrow][lk + 13] = f2tf32(pb3.y);
        Bs[lrow][lk + 14] = f2tf32(pb3.z); Bs[lrow][lk + 15] = f2tf32(pb3.w);
        __syncthreads();

        if (k0 + 32 < K) {
            pa0 = *(const float4*)(Ag + k0 + 32);
            pa1 = *(const float4*)(Ag + k0 + 36);
            pa2 = *(const float4*)(Ag + k0 + 40);
            pa3 = *(const float4*)(Ag + k0 + 44);
            pb0 = *(const float4*)(Bg + k0 + 32);
            pb1 = *(const float4*)(Bg + k0 + 36);
            pb2 = *(const float4*)(Bg + k0 + 40);
            pb3 = *(const float4*)(Bg + k0 + 44);
        }

#pragma unroll
        for (int ks = 0; ks < 4; ks++) {
            const int kb = ks * 8 + t;
            unsigned af[4][4];
#pragma unroll
            for (int mi = 0; mi < 4; mi++) {
                const int r = wm + mi * 16 + g;
                af[mi][0] = As[r][kb];
                af[mi][1] = As[r + 8][kb];
                af[mi][2] = As[r][kb + 4];
                af[mi][3] = As[r + 8][kb + 4];
            }
            unsigned bf0[4], bf1[4];
#pragma unroll
            for (int ni = 0; ni < 4; ni++) {
                const int c = wn + ni * 8 + g;
                bf0[ni] = Bs[c][kb];
                bf1[ni] = Bs[c][kb + 4];
            }
#pragma unroll
            for (int mi = 0; mi < 4; mi++)
#pragma unroll
                for (int ni = 0; ni < 4; ni++)
                    mma_tf32(acc[mi][ni], af[mi], bf0[ni], bf1[ni]);
        }
    }

    const int g2t = 2 * t;
    if (MODE == 1) {
        const int part = n0 >> 10;
        float* dstbase = (part == 0) ? g_q : (part == 1) ? g_k : g_v;
        const float qs = (part == 0) ? 0.125f : 1.0f;
#pragma unroll
        for (int mi = 0; mi < 4; mi++) {
#pragma unroll
            for (int half = 0; half < 2; half++) {
                const int m  = m0 + wm + mi * 16 + g + half * 8;
                const int bb = m >> 10;
                const int ll = m & 1023;
#pragma unroll
                for (int ni = 0; ni < 4; ni++) {
                    const int col = n0 + wn + ni * 8 + g2t;
                    const int nn  = col & 1023;
                    const int h   = nn >> 6;
                    const int d   = nn & 63;
                    float* p = dstbase +
                               (((size_t)bb * HH + h) * LL + ll) * HD + d;
                    p[0] = (acc[mi][ni][half * 2 + 0] + bias[col]) * qs;
                    p[1] = (acc[mi][ni][half * 2 + 1] + bias[col + 1]) * qs;
                }
            }
        }
    } else {
#pragma unroll
        for (int mi = 0; mi < 4; mi++) {
#pragma unroll
            for (int half = 0; half < 2; half++) {
                const int m = m0 + wm + mi * 16 + g + half * 8;
#pragma unroll
                for (int ni = 0; ni < 4; ni++) {
                    const int col = n0 + wn + ni * 8 + g2t;
                    float* p = Cout + (size_t)m * DD + col;
                    p[0] = acc[mi][ni][half * 2 + 0] + bias[col];
                    p[1] = acc[mi][ni][half * 2 + 1] + bias[col + 1];
                }
            }
        }
    }
}

// ---------------------------------------------------------------------------
// Kernel 3: tensor-core masked flash attention.
// Block = 256 threads (8 warps) x 128 queries x one (b,h). grid (8, 64).
// Each warp: 16 q-rows. Per 64-key tile:
//   S[16x64] = Q K^T (tf32 mma, Q frags register-resident),
//   mask via adjacency bitmask on fragments (sentinel -1e30, branch-free),
//   online softmax (quad shfl reductions), P -> smem (tf32),
//   O[16x64] += P V (tf32 mma).
// Smem strides: K/P = 68 (bank (4g+t)%32, conflict-free),
//               V   = 72 (bank (8t+g)%32, conflict-free).
// ---------------------------------------------------------------------------
#define PS_STR 68
#define KS_STR 68
#define VS_STR 72
#define SM_PS  0
#define SM_KS  (128 * PS_STR)
#define SM_VS  (SM_KS + 64 * KS_STR)
#define SM_TOT ((SM_VS + 64 * VS_STR) * 4)   // bytes

__global__ void __launch_bounds__(256) attn_mma_k() {
    extern __shared__ float sm[];
    float* Ps = sm + SM_PS;
    float* Ks = sm + SM_KS;
    float* Vs = sm + SM_VS;

    const int bh   = blockIdx.y;
    const int tid  = threadIdx.x;
    const int wid  = tid >> 5;
    const int lane = tid & 31;
    const int g    = lane >> 2;
    const int t    = lane & 3;
    const int q0   = blockIdx.x * 128;
    const int wrow = wid * 16;

    const float* Qg = g_q + (size_t)bh * LL * HD;
    const float* Kg = g_k + (size_t)bh * LL * HD;
    const float* Vg = g_v + (size_t)bh * LL * HD;

    // Stage Q tile into Ps (tf32), 2 threads/row, 32 floats each
    {
        const int r  = tid >> 1;
        const int c0 = (tid & 1) * 32;
        const float* src = Qg + (size_t)(q0 + r) * HD + c0;
        unsigned* dst = (unsigned*)(Ps + r * PS_STR + c0);
#pragma unroll
        for (int i = 0; i < 8; i++) {
            float4 v = *(const float4*)(src + i * 4);
            uint4 u = make_uint4(f2tf32(v.x), f2tf32(v.y), f2tf32(v.z), f2tf32(v.w));
            *(uint4*)(dst + i * 4) = u;
        }
    }
    __syncthreads();

    // Q fragments, register-resident for the whole kernel
    unsigned qf[8][4];
    {
        const unsigned* Pr0 = (const unsigned*)(Ps + (wrow + g) * PS_STR);
        const unsigned* Pr1 = (const unsigned*)(Ps + (wrow + g + 8) * PS_STR);
#pragma unroll
        for (int ks = 0; ks < 8; ks++) {
            const int kb = ks * 8 + t;
            qf[ks][0] = Pr0[kb];
            qf[ks][1] = Pr1[kb];
            qf[ks][2] = Pr0[kb + 4];
            qf[ks][3] = Pr1[kb + 4];
        }
    }

    float o[8][4];
#pragma unroll
    for (int ni = 0; ni < 8; ni++)
#pragma unroll
        for (int e = 0; e < 4; e++) o[ni][e] = 0.f;
    float m0 = NEGF, m1 = NEGF, l0 = 0.f, l1 = 0.f;

    const unsigned* adj0 = g_adj + (q0 + wrow + g) * 32;
    const unsigned* adj1 = adj0 + 8 * 32;

    for (int k0 = 0; k0 < LL; k0 += 64) {
        __syncthreads();
        // Stage K,V (tf32): 4 threads/row, 16 floats each
        {
            const int r  = tid >> 2;
            const int c0 = (tid & 3) * 16;
            const float* ksrc = Kg + (size_t)(k0 + r) * HD + c0;
            const float* vsrc = Vg + (size_t)(k0 + r) * HD + c0;
            unsigned* kd = (unsigned*)(Ks + r * KS_STR + c0);
            unsigned* vd = (unsigned*)(Vs + r * VS_STR + c0);
#pragma unroll
            for (int i = 0; i < 4; i++) {
                float4 kv = *(const float4*)(ksrc + i * 4);
                float4 vv = *(const float4*)(vsrc + i * 4);
                *(uint4*)(kd + i * 4) = make_uint4(f2tf32(kv.x), f2tf32(kv.y),
                                                   f2tf32(kv.z), f2tf32(kv.w));
                *(uint4*)(vd + i * 4) = make_uint4(f2tf32(vv.x), f2tf32(vv.y),
                                                   f2tf32(vv.z), f2tf32(vv.w));
            }
        }
        __syncthreads();

        // S = Q K^T
        float sa[8][4];
#pragma unroll
        for (int ni = 0; ni < 8; ni++)
#pragma unroll
            for (int e = 0; e < 4; e++) sa[ni][e] = 0.f;
#pragma unroll
        for (int ks = 0; ks < 8; ks++) {
            const int kb = ks * 8 + t;
#pragma unroll
            for (int ni = 0; ni < 8; ni++) {
                const unsigned* Kr = (const unsigned*)(Ks + (ni * 8 + g) * KS_STR);
                mma_tf32(sa[ni], qf[ks], Kr[kb], Kr[kb + 4]);
            }
        }

        // Mask + online softmax (branch-free)
        uint2 w0 = *(const uint2*)(adj0 + (k0 >> 5));
        uint2 w1 = *(const uint2*)(adj1 + (k0 >> 5));
        unsigned long long M0 = ((unsigned long long)w0.y << 32) | w0.x;
        unsigned long long M1 = ((unsigned long long)w1.y << 32) | w1.x;

        float tm0 = NEGF, tm1 = NEGF;
#pragma unroll
        for (int ni = 0; ni < 8; ni++) {
            const int c = ni * 8 + 2 * t;
            sa[ni][0] = ((M0 >> c) & 1ULL) ? NEGF : sa[ni][0];
            sa[ni][1] = ((M0 >> (c + 1)) & 1ULL) ? NEGF : sa[ni][1];
            sa[ni][2] = ((M1 >> c) & 1ULL) ? NEGF : sa[ni][2];
            sa[ni][3] = ((M1 >> (c + 1)) & 1ULL) ? NEGF : sa[ni][3];
            tm0 = fmaxf(tm0, fmaxf(sa[ni][0], sa[ni][1]));
            tm1 = fmaxf(tm1, fmaxf(sa[ni][2], sa[ni][3]));
        }
        tm0 = fmaxf(tm0, __shfl_xor_sync(0xffffffffu, tm0, 1));
        tm0 = fmaxf(tm0, __shfl_xor_sync(0xffffffffu, tm0, 2));
        tm1 = fmaxf(tm1, __shfl_xor_sync(0xffffffffu, tm1, 1));
        tm1 = fmaxf(tm1, __shfl_xor_sync(0xffffffffu, tm1, 2));

        const float mn0 = fmaxf(m0, tm0);
        const float mn1 = fmaxf(m1, tm1);
        const float sc0 = __expf(m0 - mn0);   // both NEGF -> exp(0)=1, l=0 anyway
        const float sc1 = __expf(m1 - mn1);
        m0 = mn0; m1 = mn1;

        float rs0 = 0.f, rs1 = 0.f;
        {
            unsigned* Pw0 = (unsigned*)(Ps + (wrow + g) * PS_STR);
            unsigned* Pw1 = (unsigned*)(Ps + (wrow + g + 8) * PS_STR);
#pragma unroll
            for (int ni = 0; ni < 8; ni++) {
                const int c = ni * 8 + 2 * t;
                float p00 = __expf(sa[ni][0] - mn0);
                float p01 = __expf(sa[ni][1] - mn0);
                float p10 = __expf(sa[ni][2] - mn1);
                float p11 = __expf(sa[ni][3] - mn1);
                rs0 += p00 + p01;
                rs1 += p10 + p11;
                Pw0[c] = f2tf32(p00); Pw0[c + 1] = f2tf32(p01);
                Pw1[c] = f2tf32(p10); Pw1[c + 1] = f2tf32(p11);
            }
        }
        rs0 += __shfl_xor_sync(0xffffffffu, rs0, 1);
        rs0 += __shfl_xor_sync(0xffffffffu, rs0, 2);
        rs1 += __shfl_xor_sync(0xffffffffu, rs1, 1);
        rs1 += __shfl_xor_sync(0xffffffffu, rs1, 2);
        l0 = l0 * sc0 + rs0;
        l1 = l1 * sc1 + rs1;
#pragma unroll
        for (int ni = 0; ni < 8; ni++) {
            o[ni][0] *= sc0; o[ni][1] *= sc0;
            o[ni][2] *= sc1; o[ni][3] *= sc1;
        }
        __syncwarp();

        // O += P V
#pragma unroll
        for (int ks = 0; ks < 8; ks++) {
            const int kb = ks * 8;
            unsigned af[4];
            af[0] = *(const unsigned*)(Ps + (wrow + g) * PS_STR + kb + t);
            af[1] = *(const unsigned*)(Ps + (wrow + g + 8) * PS_STR + kb + t);
            af[2] = *(const unsigned*)(Ps + (wrow + g) * PS_STR + kb + t + 4);
            af[3] = *(const unsigned*)(Ps + (wrow + g + 8) * PS_STR + kb + t + 4);
            const unsigned* V0 = (const unsigned*)(Vs + (kb + t) * VS_STR);
            const unsigned* V1 = (const unsigned*)(Vs + (kb + t + 4) * VS_STR);
#pragma unroll
            for (int ni = 0; ni < 8; ni++)
                mma_tf32(o[ni], af, V0[ni * 8 + g], V1[ni * 8 + g]);
        }
        __syncwarp();
    }

    // Epilogue: normalize and write [B,L,D] with head offset
    const float il0 = 1.f / l0;
    const float il1 = 1.f / l1;
    const int b = bh >> 4;
    const int h = bh & 15;
    const int qr0 = q0 + wrow + g;
    float* out0 = g_attn + ((size_t)b * LL + qr0) * DD + h * HD;
    float* out1 = g_attn + ((size_t)b * LL + qr0 + 8) * DD + h * HD;
#pragma unroll
    for (int ni = 0; ni < 8; ni++) {
        const int c = ni * 8 + 2 * t;
        float2 v0 = make_float2(o[ni][0] * il0, o[ni][1] * il0);
        float2 v1 = make_float2(o[ni][2] * il1, o[ni][3] * il1);
        *(float2*)(out0 + c) = v0;
        *(float2*)(out1 + c) = v1;
    }
}

// ---------------------------------------------------------------------------
// Launch
// ---------------------------------------------------------------------------
extern "C" void kernel_launch(void* const* d_in, const int* in_sizes, int n_in,
                              void* d_out, int out_size) {
    const float* x     = (const float*)d_in[0];   // [B,L,D]
    const int*   edges = (const int*)d_in[1];     // [E,2]
    const float* w_qkv = (const float*)d_in[2];   // [3D,D]
    const float* b_qkv = (const float*)d_in[3];   // [3D]
    const float* w_out = (const float*)d_in[4];   // [D,D]
    const float* b_out = (const float*)d_in[5];   // [D]
    float* out = (float*)d_out;                   // [B,L,D]

    // Allow >48KB dynamic smem for the attention kernel (idempotent host call)
    cudaFuncSetAttribute(attn_mma_k, cudaFuncAttributeMaxDynamicSharedMemorySize,
                         SM_TOT);

    // 1) adjacency bitmask
    adj_clear_k<<<(LL * 32 + 255) / 256, 256>>>();
    adj_scatter_k<<<(EE + 255) / 256, 256>>>(edges);

    // 2) fused QKV projection (+bias, +q scaling, +head-layout scatter) [tf32 TC]
    {
        dim3 grid(D3 / 128, (BB * LL) / 128);   // 24 x 32
        mma_gemm_k<1><<<grid, 256>>>(x, w_qkv, b_qkv, nullptr);
    }

    // 3) masked flash attention [tf32 TC]
    {
        dim3 grid(LL / 128, BB * HH);           // 8 x 64
        attn_mma_k<<<grid, 256, SM_TOT>>>();
    }

    // 4) output projection (+bias) -> d_out [tf32 TC]
    {
        dim3 grid(DD / 128, (BB * LL) / 128);   // 8 x 32
        mma_gemm_k<0><<<grid, 256>>>(nullptr, w_out, b_out, out);
    }
}

// round 6
// speedup vs baseline: 3.4767x; 1.0787x over previous
#include <cuda_runtime.h>
#include <math.h>

// Problem constants
#define BB 4
#define LL 1024
#define DD 1024
#define HH 16
#define HD 64
#define EE 16384
#define D3 3072

#define NEGF (-1e30f)

// ---------------------------------------------------------------------------
// Scratch (static device globals; no allocation allowed)
// ---------------------------------------------------------------------------
__device__ float g_q[(size_t)BB * HH * LL * HD];     // [B,H,L,HD], pre-scaled by 1/8
__device__ float g_k[(size_t)BB * HH * LL * HD];     // [B,H,L,HD]
__device__ float g_v[(size_t)BB * HH * LL * HD];     // [B,H,L,HD]
__device__ float g_attn[(size_t)BB * LL * DD];       // [B,L,D] attention output
__device__ unsigned g_adj[LL * (LL / 32)];           // bitmask: bit k of row q

// ---------------------------------------------------------------------------
// Kernel 1a: clear adjacency
// ---------------------------------------------------------------------------
__global__ void adj_clear_k() {
    int i = blockIdx.x * blockDim.x + threadIdx.x;
    if (i < LL * (LL / 32)) g_adj[i] = 0u;
}

// Kernel 1b: scatter edges (symmetric)
__global__ void adj_scatter_k(const int* __restrict__ edges) {
    int e = blockIdx.x * blockDim.x + threadIdx.x;
    if (e >= EE) return;
    int a = edges[2 * e + 0];
    int b = edges[2 * e + 1];
    atomicOr(&g_adj[a * 32 + (b >> 5)], 1u << (b & 31));
    atomicOr(&g_adj[b * 32 + (a >> 5)], 1u << (a & 31));
}

// ---------------------------------------------------------------------------
// tf32 helpers
// ---------------------------------------------------------------------------
__device__ __forceinline__ unsigned f2tf32(float f) {
    unsigned u;
    asm("cvt.rna.tf32.f32 %0, %1;" : "=r"(u) : "f"(f));
    return u;
}

__device__ __forceinline__ void mma_tf32(float* d, const unsigned* a,
                                         unsigned b0, unsigned b1) {
    asm volatile(
        "mma.sync.aligned.m16n8k8.row.col.f32.tf32.tf32.f32 "
        "{%0,%1,%2,%3}, {%4,%5,%6,%7}, {%8,%9}, {%0,%1,%2,%3};"
        : "+f"(d[0]), "+f"(d[1]), "+f"(d[2]), "+f"(d[3])
        : "r"(a[0]), "r"(a[1]), "r"(a[2]), "r"(a[3]), "r"(b0), "r"(b1));
}

// ---------------------------------------------------------------------------
// TF32 tensor-core GEMM: C[m,n] = sum_k A[m,k] * Bm[n,k] + bias[n]
// (unchanged — near legacy tf32 HMMA roofline for these shapes)
// ---------------------------------------------------------------------------
#define SSTR 36

template <int MODE>
__global__ void __launch_bounds__(256, 2) mma_gemm_k(const float* __restrict__ A_in,
                                                     const float* __restrict__ Bmat,
                                                     const float* __restrict__ bias,
                                                     float* __restrict__ Cout) {
    constexpr int K = 1024;
    const float* A = (MODE == 0) ? (const float*)g_attn : A_in;

    __shared__ unsigned As[128][SSTR];
    __shared__ unsigned Bs[128][SSTR];

    const int tid = threadIdx.x;
    const int m0 = blockIdx.y * 128;
    const int n0 = blockIdx.x * 128;

    const int lrow = tid >> 1;
    const int lk   = (tid & 1) * 16;
    const float* Ag = A    + (size_t)(m0 + lrow) * K + lk;
    const float* Bg = Bmat + (size_t)(n0 + lrow) * K + lk;

    const int wid  = tid >> 5;
    const int lane = tid & 31;
    const int wm   = (wid & 1) * 64;
    const int wn   = (wid >> 1) * 32;
    const int g    = lane >> 2;
    const int t    = lane & 3;

    float acc[4][4][4];
#pragma unroll
    for (int mi = 0; mi < 4; mi++)
#pragma unroll
        for (int ni = 0; ni < 4; ni++)
#pragma unroll
            for (int e = 0; e < 4; e++) acc[mi][ni][e] = 0.f;

    float4 pa0 = *(const float4*)(Ag + 0);
    float4 pa1 = *(const float4*)(Ag + 4);
    float4 pa2 = *(const float4*)(Ag + 8);
    float4 pa3 = *(const float4*)(Ag + 12);
    float4 pb0 = *(const float4*)(Bg + 0);
    float4 pb1 = *(const float4*)(Bg + 4);
    float4 pb2 = *(const float4*)(Bg + 8);
    float4 pb3 = *(const float4*)(Bg + 12);

    for (int k0 = 0; k0 < K; k0 += 32) {
        __syncthreads();
        As[lrow][lk + 0]  = f2tf32(pa0.x); As[lrow][lk + 1]  = f2tf32(pa0.y);
        As[lrow][lk + 2]  = f2tf32(pa0.z); As[lrow][lk + 3]  = f2tf32(pa0.w);
        As[lrow][lk + 4]  = f2tf32(pa1.x); As[lrow][lk + 5]  = f2tf32(pa1.y);
        As[lrow][lk + 6]  = f2tf32(pa1.z); As[lrow][lk + 7]  = f2tf32(pa1.w);
        As[lrow][lk + 8]  = f2tf32(pa2.x); As[lrow][lk + 9]  = f2tf32(pa2.y);
        As[lrow][lk + 10] = f2tf32(pa2.z); As[lrow][lk + 11] = f2tf32(pa2.w);
        As[lrow][lk + 12] = f2tf32(pa3.x); As[lrow][lk + 13] = f2tf32(pa3.y);
        As[lrow][lk + 14] = f2tf32(pa3.z); As[lrow][lk + 15] = f2tf32(pa3.w);
        Bs[lrow][lk + 0]  = f2tf32(pb0.x); Bs[lrow][lk + 1]  = f2tf32(pb0.y);
        Bs[lrow][lk + 2]  = f2tf32(pb0.z); Bs[lrow][lk + 3]  = f2tf32(pb0.w);
        Bs[lrow][lk + 4]  = f2tf32(pb1.x); Bs[lrow][lk + 5]  = f2tf32(pb1.y);
        Bs[lrow][lk + 6]  = f2tf32(pb1.z); Bs[lrow][lk + 7]  = f2tf32(pb1.w);
        Bs[lrow][lk + 8]  = f2tf32(pb2.x); Bs[lrow][lk + 9]  = f2tf32(pb2.y);
        Bs[lrow][lk + 10] = f2tf32(pb2.z); Bs[lrow][lk + 11] = f2tf32(pb2.w);
        Bs[lrow][lk + 12] = f2tf32(pb3.x); Bs[lrow][lk + 13] = f2tf32(pb3.y);
        Bs[lrow][lk + 14] = f2tf32(pb3.z); Bs[lrow][lk + 15] = f2tf32(pb3.w);
        __syncthreads();

        if (k0 + 32 < K) {
            pa0 = *(const float4*)(Ag + k0 + 32);
            pa1 = *(const float4*)(Ag + k0 + 36);
            pa2 = *(const float4*)(Ag + k0 + 40);
            pa3 = *(const float4*)(Ag + k0 + 44);
            pb0 = *(const float4*)(Bg + k0 + 32);
            pb1 = *(const float4*)(Bg + k0 + 36);
            pb2 = *(const float4*)(Bg + k0 + 40);
            pb3 = *(const float4*)(Bg + k0 + 44);
        }

#pragma unroll
        for (int ks = 0; ks < 4; ks++) {
            const int kb = ks * 8 + t;
            unsigned af[4][4];
#pragma unroll
            for (int mi = 0; mi < 4; mi++) {
                const int r = wm + mi * 16 + g;
                af[mi][0] = As[r][kb];
                af[mi][1] = As[r + 8][kb];
                af[mi][2] = As[r][kb + 4];
                af[mi][3] = As[r + 8][kb + 4];
            }
            unsigned bf0[4], bf1[4];
#pragma unroll
            for (int ni = 0; ni < 4; ni++) {
                const int c = wn + ni * 8 + g;
                bf0[ni] = Bs[c][kb];
                bf1[ni] = Bs[c][kb + 4];
            }
#pragma unroll
            for (int mi = 0; mi < 4; mi++)
#pragma unroll
                for (int ni = 0; ni < 4; ni++)
                    mma_tf32(acc[mi][ni], af[mi], bf0[ni], bf1[ni]);
        }
    }

    const int g2t = 2 * t;
    if (MODE == 1) {
        const int part = n0 >> 10;
        float* dstbase = (part == 0) ? g_q : (part == 1) ? g_k : g_v;
        const float qs = (part == 0) ? 0.125f : 1.0f;
#pragma unroll
        for (int mi = 0; mi < 4; mi++) {
#pragma unroll
            for (int half = 0; half < 2; half++) {
                const int m  = m0 + wm + mi * 16 + g + half * 8;
                const int bb = m >> 10;
                const int ll = m & 1023;
#pragma unroll
                for (int ni = 0; ni < 4; ni++) {
                    const int col = n0 + wn + ni * 8 + g2t;
                    const int nn  = col & 1023;
                    const int h   = nn >> 6;
                    const int d   = nn & 63;
                    float* p = dstbase +
                               (((size_t)bb * HH + h) * LL + ll) * HD + d;
                    p[0] = (acc[mi][ni][half * 2 + 0] + bias[col]) * qs;
                    p[1] = (acc[mi][ni][half * 2 + 1] + bias[col + 1]) * qs;
                }
            }
        }
    } else {
#pragma unroll
        for (int mi = 0; mi < 4; mi++) {
#pragma unroll
            for (int half = 0; half < 2; half++) {
                const int m = m0 + wm + mi * 16 + g + half * 8;
#pragma unroll
                for (int ni = 0; ni < 4; ni++) {
                    const int col = n0 + wn + ni * 8 + g2t;
                    float* p = Cout + (size_t)m * DD + col;
                    p[0] = acc[mi][ni][half * 2 + 0] + bias[col];
                    p[1] = acc[mi][ni][half * 2 + 1] + bias[col + 1];
                }
            }
        }
    }
}

// ---------------------------------------------------------------------------
// Kernel 3: tensor-core masked flash attention, v2.
// Block = 256 threads (8 warps), 128 queries x one (b,h). grid (8, 64).
// v2 changes vs v1:
//   - __launch_bounds__(256, 2): 2 resident blocks/SM (regs capped at 128)
//   - no P smem: S-frag -> PV A-frag via quad shuffles (FA2-style permute)
//   - Q fragments loaded directly from global (once), no Q staging buffer
// Smem: K stride 68 (bank (4g+t)%32), V stride 72 (bank (8t+g)%32); both
// conflict-free. Total static smem 35.8KB -> occupancy limited by regs only.
// ---------------------------------------------------------------------------
#define KS_STR 68
#define VS_STR 72

__global__ void __launch_bounds__(256, 2) attn_mma_k() {
    __shared__ float Ks[64 * KS_STR];
    __shared__ float Vs[64 * VS_STR];

    const int bh   = blockIdx.y;
    const int tid  = threadIdx.x;
    const int wid  = tid >> 5;
    const int lane = tid & 31;
    const int g    = lane >> 2;
    const int t    = lane & 3;
    const int q0   = blockIdx.x * 128;
    const int wrow = wid * 16;

    const float* Qg = g_q + (size_t)bh * LL * HD;
    const float* Kg = g_k + (size_t)bh * LL * HD;
    const float* Vg = g_v + (size_t)bh * LL * HD;

    // Q fragments: load directly from global (register-resident all kernel)
    unsigned qf[8][4];
    {
        const float* Q0 = Qg + (size_t)(q0 + wrow + g) * HD;
        const float* Q1 = Q0 + 8 * HD;
#pragma unroll
        for (int ks = 0; ks < 8; ks++) {
            qf[ks][0] = f2tf32(Q0[ks * 8 + t]);
            qf[ks][1] = f2tf32(Q1[ks * 8 + t]);
            qf[ks][2] = f2tf32(Q0[ks * 8 + t + 4]);
            qf[ks][3] = f2tf32(Q1[ks * 8 + t + 4]);
        }
    }

    float o[8][4];
#pragma unroll
    for (int nj = 0; nj < 8; nj++)
#pragma unroll
        for (int e = 0; e < 4; e++) o[nj][e] = 0.f;
    float m0 = NEGF, m1 = NEGF, l0 = 0.f, l1 = 0.f;

    const unsigned* adj0 = g_adj + (q0 + wrow + g) * 32;
    const unsigned* adj1 = adj0 + 8 * 32;
    const int srcLo = (lane & ~3) | (t >> 1);   // quad lane holding col t
    const int srcHi = srcLo + 2;                // quad lane holding col t+4
    const bool oddT = (t & 1);

    for (int k0 = 0; k0 < LL; k0 += 64) {
        __syncthreads();
        // Stage K,V (tf32): 4 threads/row, 16 floats each
        {
            const int r  = tid >> 2;
            const int c0 = (tid & 3) * 16;
            const float* ksrc = Kg + (size_t)(k0 + r) * HD + c0;
            const float* vsrc = Vg + (size_t)(k0 + r) * HD + c0;
            unsigned* kd = (unsigned*)(Ks + r * KS_STR + c0);
            unsigned* vd = (unsigned*)(Vs + r * VS_STR + c0);
#pragma unroll
            for (int i = 0; i < 4; i++) {
                float4 kv = *(const float4*)(ksrc + i * 4);
                float4 vv = *(const float4*)(vsrc + i * 4);
                *(uint4*)(kd + i * 4) = make_uint4(f2tf32(kv.x), f2tf32(kv.y),
                                                   f2tf32(kv.z), f2tf32(kv.w));
                *(uint4*)(vd + i * 4) = make_uint4(f2tf32(vv.x), f2tf32(vv.y),
                                                   f2tf32(vv.z), f2tf32(vv.w));
            }
        }
        __syncthreads();

        // S = Q K^T   (sa[ni] covers key cols ni*8..ni*8+7)
        float sa[8][4];
#pragma unroll
        for (int ni = 0; ni < 8; ni++)
#pragma unroll
            for (int e = 0; e < 4; e++) sa[ni][e] = 0.f;
#pragma unroll
        for (int ks = 0; ks < 8; ks++) {
            const int kb = ks * 8 + t;
#pragma unroll
            for (int ni = 0; ni < 8; ni++) {
                const unsigned* Kr = (const unsigned*)(Ks + (ni * 8 + g) * KS_STR);
                mma_tf32(sa[ni], qf[ks], Kr[kb], Kr[kb + 4]);
            }
        }

        // Mask + tile row-max (branch-free)
        uint2 w0 = *(const uint2*)(adj0 + (k0 >> 5));
        uint2 w1 = *(const uint2*)(adj1 + (k0 >> 5));
        unsigned long long M0 = ((unsigned long long)w0.y << 32) | w0.x;
        unsigned long long M1 = ((unsigned long long)w1.y << 32) | w1.x;

        float tm0 = NEGF, tm1 = NEGF;
#pragma unroll
        for (int ni = 0; ni < 8; ni++) {
            const int c = ni * 8 + 2 * t;
            sa[ni][0] = ((M0 >> c) & 1ULL) ? NEGF : sa[ni][0];
            sa[ni][1] = ((M0 >> (c + 1)) & 1ULL) ? NEGF : sa[ni][1];
            sa[ni][2] = ((M1 >> c) & 1ULL) ? NEGF : sa[ni][2];
            sa[ni][3] = ((M1 >> (c + 1)) & 1ULL) ? NEGF : sa[ni][3];
            tm0 = fmaxf(tm0, fmaxf(sa[ni][0], sa[ni][1]));
            tm1 = fmaxf(tm1, fmaxf(sa[ni][2], sa[ni][3]));
        }
        tm0 = fmaxf(tm0, __shfl_xor_sync(0xffffffffu, tm0, 1));
        tm0 = fmaxf(tm0, __shfl_xor_sync(0xffffffffu, tm0, 2));
        tm1 = fmaxf(tm1, __shfl_xor_sync(0xffffffffu, tm1, 1));
        tm1 = fmaxf(tm1, __shfl_xor_sync(0xffffffffu, tm1, 2));

        const float mn0 = fmaxf(m0, tm0);
        const float mn1 = fmaxf(m1, tm1);
        const float sc0 = __expf(m0 - mn0);
        const float sc1 = __expf(m1 - mn1);
        m0 = mn0; m1 = mn1;

        // Rescale O before accumulating this tile
#pragma unroll
        for (int nj = 0; nj < 8; nj++) {
            o[nj][0] *= sc0; o[nj][1] *= sc0;
            o[nj][2] *= sc1; o[nj][3] *= sc1;
        }

        // Fused softmax + PV: per key-block ni, exp -> shuffle to A-frag -> mma
        float rs0 = 0.f, rs1 = 0.f;
#pragma unroll
        for (int ni = 0; ni < 8; ni++) {
            float p00 = __expf(sa[ni][0] - mn0);
            float p01 = __expf(sa[ni][1] - mn0);
            float p10 = __expf(sa[ni][2] - mn1);
            float p11 = __expf(sa[ni][3] - mn1);
            rs0 += p00 + p01;
            rs1 += p10 + p11;

            unsigned u0 = f2tf32(p00), u1 = f2tf32(p01);
            unsigned u2 = f2tf32(p10), u3 = f2tf32(p11);

            // A-frag permute: af0=P[g][t], af1=P[g+8][t], af2=P[g][t+4], af3=P[g+8][t+4]
            unsigned af[4];
            unsigned x0 = __shfl_sync(0xffffffffu, u0, srcLo);
            unsigned x1 = __shfl_sync(0xffffffffu, u1, srcLo);
            af[0] = oddT ? x1 : x0;
            unsigned y0 = __shfl_sync(0xffffffffu, u2, srcLo);
            unsigned y1 = __shfl_sync(0xffffffffu, u3, srcLo);
            af[1] = oddT ? y1 : y0;
            unsigned z0 = __shfl_sync(0xffffffffu, u0, srcHi);
            unsigned z1 = __shfl_sync(0xffffffffu, u1, srcHi);
            af[2] = oddT ? z1 : z0;
            unsigned w2 = __shfl_sync(0xffffffffu, u2, srcHi);
            unsigned w3 = __shfl_sync(0xffffffffu, u3, srcHi);
            af[3] = oddT ? w3 : w2;

            const unsigned* V0 = (const unsigned*)(Vs + (ni * 8 + t) * VS_STR);
            const unsigned* V1 = (const unsigned*)(Vs + (ni * 8 + t + 4) * VS_STR);
#pragma unroll
            for (int nj = 0; nj < 8; nj++)
                mma_tf32(o[nj], af, V0[nj * 8 + g], V1[nj * 8 + g]);
        }
        rs0 += __shfl_xor_sync(0xffffffffu, rs0, 1);
        rs0 += __shfl_xor_sync(0xffffffffu, rs0, 2);
        rs1 += __shfl_xor_sync(0xffffffffu, rs1, 1);
        rs1 += __shfl_xor_sync(0xffffffffu, rs1, 2);
        l0 = l0 * sc0 + rs0;
        l1 = l1 * sc1 + rs1;
    }

    // Epilogue: normalize and write [B,L,D] with head offset
    const float il0 = 1.f / l0;
    const float il1 = 1.f / l1;
    const int b = bh >> 4;
    const int h = bh & 15;
    const int qr0 = q0 + wrow + g;
    float* out0 = g_attn + ((size_t)b * LL + qr0) * DD + h * HD;
    float* out1 = g_attn + ((size_t)b * LL + qr0 + 8) * DD + h * HD;
#pragma unroll
    for (int nj = 0; nj < 8; nj++) {
        const int c = nj * 8 + 2 * t;
        float2 v0 = make_float2(o[nj][0] * il0, o[nj][1] * il0);
        float2 v1 = make_float2(o[nj][2] * il1, o[nj][3] * il1);
        *(float2*)(out0 + c) = v0;
        *(float2*)(out1 + c) = v1;
    }
}

// ---------------------------------------------------------------------------
// Launch
// ---------------------------------------------------------------------------
extern "C" void kernel_launch(void* const* d_in, const int* in_sizes, int n_in,
                              void* d_out, int out_size) {
    const float* x     = (const float*)d_in[0];   // [B,L,D]
    const int*   edges = (const int*)d_in[1];     // [E,2]
    const float* w_qkv = (const float*)d_in[2];   // [3D,D]
    const float* b_qkv = (const float*)d_in[3];   // [3D]
    const float* w_out = (const float*)d_in[4];   // [D,D]
    const float* b_out = (const float*)d_in[5];   // [D]
    float* out = (float*)d_out;                   // [B,L,D]

    // 1) adjacency bitmask
    adj_clear_k<<<(LL * 32 + 255) / 256, 256>>>();
    adj_scatter_k<<<(EE + 255) / 256, 256>>>(edges);

    // 2) fused QKV projection (+bias, +q scaling, +head-layout scatter) [tf32 TC]
    {
        dim3 grid(D3 / 128, (BB * LL) / 128);   // 24 x 32
        mma_gemm_k<1><<<grid, 256>>>(x, w_qkv, b_qkv, nullptr);
    }

    // 3) masked flash attention [tf32 TC, 2 blocks/SM]
    {
        dim3 grid(LL / 128, BB * HH);           // 8 x 64
        attn_mma_k<<<grid, 256>>>();
    }

    // 4) output projection (+bias) -> d_out [tf32 TC]
    {
        dim3 grid(DD / 128, (BB * LL) / 128);   // 8 x 32
        mma_gemm_k<0><<<grid, 256>>>(nullptr, w_out, b_out, out);
    }
}

// round 9
// speedup vs baseline: 3.5139x; 1.0107x over previous
#include <cuda_runtime.h>
#include <math.h>
#include <stdint.h>

// Problem constants
#define BB 4
#define LL 1024
#define DD 1024
#define HH 16
#define HD 64
#define EE 16384
#define D3 3072

#define NEGF (-1e30f)

// ---------------------------------------------------------------------------
// Scratch (static device globals; no allocation allowed)
// ---------------------------------------------------------------------------
__device__ float g_q[(size_t)BB * HH * LL * HD];     // [B,H,L,HD], pre-scaled by 1/8, tf32-rounded
__device__ float g_k[(size_t)BB * HH * LL * HD];     // [B,H,L,HD], tf32-rounded
__device__ float g_v[(size_t)BB * HH * LL * HD];     // [B,H,L,HD], tf32-rounded
__device__ float g_attn[(size_t)BB * LL * DD];       // [B,L,D] attention output
__device__ unsigned g_adj[LL * (LL / 32)];           // bitmask: bit k of row q

// ---------------------------------------------------------------------------
// Kernel 1: adjacency
// ---------------------------------------------------------------------------
__global__ void adj_clear_k() {
    int i = blockIdx.x * blockDim.x + threadIdx.x;
    if (i < LL * (LL / 32)) g_adj[i] = 0u;
}

__global__ void adj_scatter_k(const int* __restrict__ edges) {
    int e = blockIdx.x * blockDim.x + threadIdx.x;
    if (e >= EE) return;
    int a = edges[2 * e + 0];
    int b = edges[2 * e + 1];
    atomicOr(&g_adj[a * 32 + (b >> 5)], 1u << (b & 31));
    atomicOr(&g_adj[b * 32 + (a >> 5)], 1u << (a & 31));
}

// ---------------------------------------------------------------------------
// Helpers
// ---------------------------------------------------------------------------
__device__ __forceinline__ unsigned f2tf32(float f) {
    unsigned u;
    asm("cvt.rna.tf32.f32 %0, %1;" : "=r"(u) : "f"(f));
    return u;
}

__device__ __forceinline__ void mma_tf32(float* d, const unsigned* a,
                                         unsigned b0, unsigned b1) {
    asm volatile(
        "mma.sync.aligned.m16n8k8.row.col.f32.tf32.tf32.f32 "
        "{%0,%1,%2,%3}, {%4,%5,%6,%7}, {%8,%9}, {%0,%1,%2,%3};"
        : "+f"(d[0]), "+f"(d[1]), "+f"(d[2]), "+f"(d[3])
        : "r"(a[0]), "r"(a[1]), "r"(a[2]), "r"(a[3]), "r"(b0), "r"(b1));
}

__device__ __forceinline__ uint32_t smem_u32(const void* p) {
    uint32_t a;
    asm("{ .reg .u64 t; cvta.to.shared.u64 t, %1; cvt.u32.u64 %0, t; }"
        : "=r"(a) : "l"(p));
    return a;
}

__device__ __forceinline__ void cp_async16(uint32_t saddr, const void* gptr) {
    asm volatile("cp.async.cg.shared.global [%0], [%1], 16;"
                 :: "r"(saddr), "l"(gptr) : "memory");
}
__device__ __forceinline__ void cp_commit() {
    asm volatile("cp.async.commit_group;" ::: "memory");
}
template <int N>
__device__ __forceinline__ void cp_wait() {
    asm volatile("cp.async.wait_group %0;" :: "n"(N) : "memory");
}

// ---------------------------------------------------------------------------
// TF32 tensor-core GEMM (mma.sync): C[m,n] = sum_k A[m,k]*Bm[n,k] + bias[n]
// BM=BN=128, BK=32, 256 threads = 8 warps, warp tile 64x32, m16n8k8.
// MODE 1: QKV -> scatter to g_q/g_k/g_v (tf32-rounded), q scaled 0.125
// MODE 0: out-proj from g_attn -> Cout row-major
// ---------------------------------------------------------------------------
#define SSTR 36

template <int MODE>
__global__ void __launch_bounds__(256, 2) mma_gemm_k(const float* __restrict__ A_in,
                                                     const float* __restrict__ Bmat,
                                                     const float* __restrict__ bias,
                                                     float* __restrict__ Cout) {
    constexpr int K = 1024;
    const float* A = (MODE == 0) ? (const float*)g_attn : A_in;

    __shared__ unsigned As[128][SSTR];
    __shared__ unsigned Bs[128][SSTR];

    const int tid = threadIdx.x;
    const int m0 = blockIdx.y * 128;
    const int n0 = blockIdx.x * 128;

    const int lrow = tid >> 1;
    const int lk   = (tid & 1) * 16;
    const float* Ag = A    + (size_t)(m0 + lrow) * K + lk;
    const float* Bg = Bmat + (size_t)(n0 + lrow) * K + lk;

    const int wid  = tid >> 5;
    const int lane = tid & 31;
    const int wm   = (wid & 1) * 64;
    const int wn   = (wid >> 1) * 32;
    const int g    = lane >> 2;
    const int t    = lane & 3;

    float acc[4][4][4];
#pragma unroll
    for (int mi = 0; mi < 4; mi++)
#pragma unroll
        for (int ni = 0; ni < 4; ni++)
#pragma unroll
            for (int e = 0; e < 4; e++) acc[mi][ni][e] = 0.f;

    float4 pa[4], pb[4];
#pragma unroll
    for (int j = 0; j < 4; j++) {
        pa[j] = *(const float4*)(Ag + 4 * j);
        pb[j] = *(const float4*)(Bg + 4 * j);
    }

    for (int k0 = 0; k0 < K; k0 += 32) {
        __syncthreads();
#pragma unroll
        for (int j = 0; j < 4; j++) {
            *(uint4*)&As[lrow][lk + 4 * j] =
                make_uint4(f2tf32(pa[j].x), f2tf32(pa[j].y),
                           f2tf32(pa[j].z), f2tf32(pa[j].w));
            *(uint4*)&Bs[lrow][lk + 4 * j] =
                make_uint4(f2tf32(pb[j].x), f2tf32(pb[j].y),
                           f2tf32(pb[j].z), f2tf32(pb[j].w));
        }
        __syncthreads();

        if (k0 + 32 < K) {
#pragma unroll
            for (int j = 0; j < 4; j++) {
                pa[j] = *(const float4*)(Ag + k0 + 32 + 4 * j);
                pb[j] = *(const float4*)(Bg + k0 + 32 + 4 * j);
            }
        }

#pragma unroll
        for (int ks = 0; ks < 4; ks++) {
            const int kb = ks * 8 + t;
            unsigned af[4][4];
#pragma unroll
            for (int mi = 0; mi < 4; mi++) {
                const int r = wm + mi * 16 + g;
                af[mi][0] = As[r][kb];
                af[mi][1] = As[r + 8][kb];
                af[mi][2] = As[r][kb + 4];
                af[mi][3] = As[r + 8][kb + 4];
            }
            unsigned bf0[4], bf1[4];
#pragma unroll
            for (int ni = 0; ni < 4; ni++) {
                const int c = wn + ni * 8 + g;
                bf0[ni] = Bs[c][kb];
                bf1[ni] = Bs[c][kb + 4];
            }
#pragma unroll
            for (int mi = 0; mi < 4; mi++)
#pragma unroll
                for (int ni = 0; ni < 4; ni++)
                    mma_tf32(acc[mi][ni], af[mi], bf0[ni], bf1[ni]);
        }
    }

    const int g2t = 2 * t;
    if (MODE == 1) {
        const int part = n0 >> 10;
        float* dstbase = (part == 0) ? g_q : (part == 1) ? g_k : g_v;
        const float qs = (part == 0) ? 0.125f : 1.0f;
#pragma unroll
        for (int mi = 0; mi < 4; mi++) {
#pragma unroll
            for (int half = 0; half < 2; half++) {
                const int m  = m0 + wm + mi * 16 + g + half * 8;
                const int bb = m >> 10;
                const int ll = m & 1023;
#pragma unroll
                for (int ni = 0; ni < 4; ni++) {
                    const int col = n0 + wn + ni * 8 + g2t;
                    const int nn  = col & 1023;
                    const int h   = nn >> 6;
                    const int d   = nn & 63;
                    float* p = dstbase +
                               (((size_t)bb * HH + h) * LL + ll) * HD + d;
                    // Store tf32-rounded so attention can cp.async raw fp32
                    // with numerics identical to an explicit cvt at staging.
                    p[0] = __uint_as_float(f2tf32((acc[mi][ni][half * 2 + 0] + bias[col]) * qs));
                    p[1] = __uint_as_float(f2tf32((acc[mi][ni][half * 2 + 1] + bias[col + 1]) * qs));
                }
            }
        }
    } else {
#pragma unroll
        for (int mi = 0; mi < 4; mi++) {
#pragma unroll
            for (int half = 0; half < 2; half++) {
                const int m = m0 + wm + mi * 16 + g + half * 8;
#pragma unroll
                for (int ni = 0; ni < 4; ni++) {
                    const int col = n0 + wn + ni * 8 + g2t;
                    float* p = Cout + (size_t)m * DD + col;
                    p[0] = acc[mi][ni][half * 2 + 0] + bias[col];
                    p[1] = acc[mi][ni][half * 2 + 1] + bias[col + 1];
                }
            }
        }
    }
}

// ---------------------------------------------------------------------------
// Kernel 3: tensor-core masked flash attention, v3.
// v3: cp.async double-buffered K/V staging (2-deep pipeline, dynamic smem).
// K/V are pre-rounded to tf32 by the QKV epilogue, so raw 16B copies keep
// numerics identical to v2. Q fragments loaded from global (cvt, idempotent).
// Block = 256 threads (8 warps), 128 queries x one (b,h). grid (8, 64).
// ---------------------------------------------------------------------------
#define KS_STR 68
#define VS_STR 72
#define STAGE_W (64 * (KS_STR + VS_STR))          // floats per stage buffer
#define ATTN_SMEM (2 * STAGE_W * 4)               // 71680 bytes

__global__ void __launch_bounds__(256, 2) attn_mma_k() {
    extern __shared__ float sm[];

    const int bh   = blockIdx.y;
    const int tid  = threadIdx.x;
    const int wid  = tid >> 5;
    const int lane = tid & 31;
    const int g    = lane >> 2;
    const int t    = lane & 3;
    const int q0   = blockIdx.x * 128;
    const int wrow = wid * 16;

    const float* Qg = g_q + (size_t)bh * LL * HD;
    const float* Kg = g_k + (size_t)bh * LL * HD;
    const float* Vg = g_v + (size_t)bh * LL * HD;

    // Staging geometry: 4 threads/row, 16 floats (4x16B) each for K and V
    const int srow = tid >> 2;
    const int scol = (tid & 3) * 16;
    const float* kg0 = Kg + (size_t)srow * HD + scol;
    const float* vg0 = Vg + (size_t)srow * HD + scol;
    uint32_t kd0 = smem_u32(sm + srow * KS_STR + scol);
    uint32_t vd0 = smem_u32(sm + 64 * KS_STR + srow * VS_STR + scol);

    // Q fragments: register-resident all kernel
    unsigned qf[8][4];
    {
        const float* Q0 = Qg + (size_t)(q0 + wrow + g) * HD;
        const float* Q1 = Q0 + 8 * HD;
#pragma unroll
        for (int ks = 0; ks < 8; ks++) {
            qf[ks][0] = f2tf32(Q0[ks * 8 + t]);
            qf[ks][1] = f2tf32(Q1[ks * 8 + t]);
            qf[ks][2] = f2tf32(Q0[ks * 8 + t + 4]);
            qf[ks][3] = f2tf32(Q1[ks * 8 + t + 4]);
        }
    }

    // Prologue: stage tiles 0 and 1
#pragma unroll
    for (int it = 0; it < 2; it++) {
        const uint32_t soff = it * STAGE_W * 4;
        const size_t goff = (size_t)it * 64 * HD;
#pragma unroll
        for (int i = 0; i < 4; i++) {
            cp_async16(kd0 + soff + i * 16, kg0 + goff + i * 4);
            cp_async16(vd0 + soff + i * 16, vg0 + goff + i * 4);
        }
        cp_commit();
    }

    float o[8][4];
#pragma unroll
    for (int nj = 0; nj < 8; nj++)
#pragma unroll
        for (int e = 0; e < 4; e++) o[nj][e] = 0.f;
    float m0 = NEGF, m1 = NEGF, l0 = 0.f, l1 = 0.f;

    const unsigned* adj0 = g_adj + (q0 + wrow + g) * 32;
    const unsigned* adj1 = adj0 + 8 * 32;
    const int srcLo = (lane & ~3) | (t >> 1);
    const int srcHi = srcLo + 2;
    const bool oddT = (t & 1);

#pragma unroll 1
    for (int it = 0; it < 16; it++) {
        const int buf = it & 1;
        const int k0 = it * 64;
        if (it < 15) cp_wait<1>(); else cp_wait<0>();
        __syncthreads();

        const float* Ks = sm + buf * STAGE_W;
        const float* Vs = Ks + 64 * KS_STR;

        // S = Q K^T
        float sa[8][4];
#pragma unroll
        for (int ni = 0; ni < 8; ni++)
#pragma unroll
            for (int e = 0; e < 4; e++) sa[ni][e] = 0.f;
#pragma unroll
        for (int ks = 0; ks < 8; ks++) {
            const int kb = ks * 8 + t;
#pragma unroll
            for (int ni = 0; ni < 8; ni++) {
                const unsigned* Kr = (const unsigned*)(Ks + (ni * 8 + g) * KS_STR);
                mma_tf32(sa[ni], qf[ks], Kr[kb], Kr[kb + 4]);
            }
        }

        // Mask + tile row-max
        uint2 w0 = *(const uint2*)(adj0 + (k0 >> 5));
        uint2 w1 = *(const uint2*)(adj1 + (k0 >> 5));
        unsigned long long M0 = ((unsigned long long)w0.y << 32) | w0.x;
        unsigned long long M1 = ((unsigned long long)w1.y << 32) | w1.x;

        float tm0 = NEGF, tm1 = NEGF;
#pragma unroll
        for (int ni = 0; ni < 8; ni++) {
            const int c = ni * 8 + 2 * t;
            sa[ni][0] = ((M0 >> c) & 1ULL) ? NEGF : sa[ni][0];
            sa[ni][1] = ((M0 >> (c + 1)) & 1ULL) ? NEGF : sa[ni][1];
            sa[ni][2] = ((M1 >> c) & 1ULL) ? NEGF : sa[ni][2];
            sa[ni][3] = ((M1 >> (c + 1)) & 1ULL) ? NEGF : sa[ni][3];
            tm0 = fmaxf(tm0, fmaxf(sa[ni][0], sa[ni][1]));
            tm1 = fmaxf(tm1, fmaxf(sa[ni][2], sa[ni][3]));
        }
        tm0 = fmaxf(tm0, __shfl_xor_sync(0xffffffffu, tm0, 1));
        tm0 = fmaxf(tm0, __shfl_xor_sync(0xffffffffu, tm0, 2));
        tm1 = fmaxf(tm1, __shfl_xor_sync(0xffffffffu, tm1, 1));
        tm1 = fmaxf(tm1, __shfl_xor_sync(0xffffffffu, tm1, 2));

        const float mn0 = fmaxf(m0, tm0);
        const float mn1 = fmaxf(m1, tm1);
        const float sc0 = __expf(m0 - mn0);
        const float sc1 = __expf(m1 - mn1);
        m0 = mn0; m1 = mn1;

#pragma unroll
        for (int nj = 0; nj < 8; nj++) {
            o[nj][0] *= sc0; o[nj][1] *= sc0;
            o[nj][2] *= sc1; o[nj][3] *= sc1;
        }

        // Fused softmax + PV via register permute
        float rs0 = 0.f, rs1 = 0.f;
#pragma unroll
        for (int ni = 0; ni < 8; ni++) {
            float p00 = __expf(sa[ni][0] - mn0);
            float p01 = __expf(sa[ni][1] - mn0);
            float p10 = __expf(sa[ni][2] - mn1);
            float p11 = __expf(sa[ni][3] - mn1);
            rs0 += p00 + p01;
            rs1 += p10 + p11;

            unsigned u0 = f2tf32(p00), u1 = f2tf32(p01);
            unsigned u2 = f2tf32(p10), u3 = f2tf32(p11);

            unsigned af[4];
            unsigned x0 = __shfl_sync(0xffffffffu, u0, srcLo);
            unsigned x1 = __shfl_sync(0xffffffffu, u1, srcLo);
            af[0] = oddT ? x1 : x0;
            unsigned y0 = __shfl_sync(0xffffffffu, u2, srcLo);
            unsigned y1 = __shfl_sync(0xffffffffu, u3, srcLo);
            af[1] = oddT ? y1 : y0;
            unsigned z0 = __shfl_sync(0xffffffffu, u0, srcHi);
            unsigned z1 = __shfl_sync(0xffffffffu, u1, srcHi);
            af[2] = oddT ? z1 : z0;
            unsigned w2 = __shfl_sync(0xffffffffu, u2, srcHi);
            unsigned w3 = __shfl_sync(0xffffffffu, u3, srcHi);
            af[3] = oddT ? w3 : w2;

            const unsigned* V0 = (const unsigned*)(Vs + (ni * 8 + t) * VS_STR);
            const unsigned* V1 = (const unsigned*)(Vs + (ni * 8 + t + 4) * VS_STR);
#pragma unroll
            for (int nj = 0; nj < 8; nj++)
                mma_tf32(o[nj], af, V0[nj * 8 + g], V1[nj * 8 + g]);
        }
        rs0 += __shfl_xor_sync(0xffffffffu, rs0, 1);
        rs0 += __shfl_xor_sync(0xffffffffu, rs0, 2);
        rs1 += __shfl_xor_sync(0xffffffffu, rs1, 1);
        rs1 += __shfl_xor_sync(0xffffffffu, rs1, 2);
        l0 = l0 * sc0 + rs0;
        l1 = l1 * sc1 + rs1;

        __syncthreads();   // compute on buf done -> safe to restage buf
        if (it + 2 < 16) {
            const uint32_t soff = buf * STAGE_W * 4;
            const size_t goff = (size_t)(it + 2) * 64 * HD;
#pragma unroll
            for (int i = 0; i < 4; i++) {
                cp_async16(kd0 + soff + i * 16, kg0 + goff + i * 4);
                cp_async16(vd0 + soff + i * 16, vg0 + goff + i * 4);
            }
            cp_commit();
        }
    }

    // Epilogue: normalize and write [B,L,D] with head offset
    const float il0 = 1.f / l0;
    const float il1 = 1.f / l1;
    const int b = bh >> 4;
    const int h = bh & 15;
    const int qr0 = q0 + wrow + g;
    float* out0 = g_attn + ((size_t)b * LL + qr0) * DD + h * HD;
    float* out1 = g_attn + ((size_t)b * LL + qr0 + 8) * DD + h * HD;
#pragma unroll
    for (int nj = 0; nj < 8; nj++) {
        const int c = nj * 8 + 2 * t;
        float2 v0 = make_float2(o[nj][0] * il0, o[nj][1] * il0);
        float2 v1 = make_float2(o[nj][2] * il1, o[nj][3] * il1);
        *(float2*)(out0 + c) = v0;
        *(float2*)(out1 + c) = v1;
    }
}

// ---------------------------------------------------------------------------
// Launch
// ---------------------------------------------------------------------------
extern "C" void kernel_launch(void* const* d_in, const int* in_sizes, int n_in,
                              void* d_out, int out_size) {
    const float* x     = (const float*)d_in[0];   // [B,L,D]
    const int*   edges = (const int*)d_in[1];     // [E,2]
    const float* w_qkv = (const float*)d_in[2];   // [3D,D]
    const float* b_qkv = (const float*)d_in[3];   // [3D]
    const float* w_out = (const float*)d_in[4];   // [D,D]
    const float* b_out = (const float*)d_in[5];   // [D]
    float* out = (float*)d_out;                   // [B,L,D]

    // >48KB dynamic smem for the attention kernel (host attr, capture-safe)
    cudaFuncSetAttribute(attn_mma_k, cudaFuncAttributeMaxDynamicSharedMemorySize,
                         ATTN_SMEM);

    // 1) adjacency bitmask
    adj_clear_k<<<(LL * 32 + 255) / 256, 256>>>();
    adj_scatter_k<<<(EE + 255) / 256, 256>>>(edges);

    // 2) fused QKV projection (+bias, +q scaling, +head scatter) [tf32 TC]
    {
        dim3 grid(D3 / 128, (BB * LL) / 128);   // 24 x 32
        mma_gemm_k<1><<<grid, 256>>>(x, w_qkv, b_qkv, nullptr);
    }

    // 3) masked flash attention [tf32 TC, cp.async pipeline, 2 blocks/SM]
    {
        dim3 grid(LL / 128, BB * HH);           // 8 x 64
        attn_mma_k<<<grid, 256, ATTN_SMEM>>>();
    }

    // 4) output projection (+bias) -> d_out [tf32 TC]
    {
        dim3 grid(DD / 128, (BB * LL) / 128);   // 8 x 32
        mma_gemm_k<0><<<grid, 256>>>(nullptr, w_out, b_out, out);
    }
}